// round 6
// baseline (speedup 1.0000x reference)
#include <cuda_runtime.h>
#include <cstddef>

// Integrate-and-fire scan, TBN layout, pure HBM-streaming problem.
//   m_t = v_{t-1} + x_t ;  y_t = (m_t >= 1) ;  v_t = m_t - y_t
//
// R5: 256-bit global accesses (Blackwell ld/st.global.v8.f32).
// Each thread owns 8 consecutive floats of the B*N dimension; scans T=32
// in registers. 1 KB per warp per request -> longer DRAM bursts, half the
// LDG/STG instruction and L1tex-wavefront count of the float4 version.

#define T_STEPS 32

__global__ void __launch_bounds__(256) if_scan_kernel(
    const float* __restrict__ x, float* __restrict__ y, int bn)
{
    const size_t i = (size_t)(blockIdx.x * blockDim.x + threadIdx.x) * 8;

    const float* xp = x + i;
    float*       yp = y + i;

    float v[8], m[8], s[8];
    #pragma unroll
    for (int j = 0; j < 8; j++) v[j] = 0.0f;

    #pragma unroll
    for (int t = 0; t < T_STEPS; t++) {
        const float* px = xp + (size_t)t * (size_t)bn;
        asm volatile(
            "ld.global.v8.f32 {%0,%1,%2,%3,%4,%5,%6,%7}, [%8];"
            : "=f"(m[0]), "=f"(m[1]), "=f"(m[2]), "=f"(m[3]),
              "=f"(m[4]), "=f"(m[5]), "=f"(m[6]), "=f"(m[7])
            : "l"(px));

        #pragma unroll
        for (int j = 0; j < 8; j++) {
            m[j] += v[j];
            s[j] = (m[j] >= 1.0f) ? 1.0f : 0.0f;
            v[j] = m[j] - s[j];
        }

        float* py = yp + (size_t)t * (size_t)bn;
        asm volatile(
            "st.global.v8.f32 [%0], {%1,%2,%3,%4,%5,%6,%7,%8};"
            :: "l"(py),
               "f"(s[0]), "f"(s[1]), "f"(s[2]), "f"(s[3]),
               "f"(s[4]), "f"(s[5]), "f"(s[6]), "f"(s[7])
            : "memory");
    }
}

extern "C" void kernel_launch(void* const* d_in, const int* in_sizes, int n_in,
                              void* d_out, int out_size)
{
    const float* x = (const float*)d_in[0];
    float* y = (float*)d_out;

    int total = in_sizes[0];           // T*B*N
    int bn = total / T_STEPS;          // B*N = 2097152

    int threads = 256;
    int blocks = bn / (8 * threads);   // 1024, exact division, no tail
    if_scan_kernel<<<blocks, threads>>>(x, y, bn);
}

// round 7
// speedup vs baseline: 1.0695x; 1.0695x over previous
#include <cuda_runtime.h>

// Integrate-and-fire scan, TBN layout, pure HBM-streaming problem.
//   m_t = v_{t-1} + x_t ;  y_t = (m_t >= 1) ;  v_t = m_t - y_t
//
// R6: pairwise t-processing. Two loads in flight (MLP=2, below the B300
// cross-CTA L1tex-queue contention threshold), two STG.128 issued
// back-to-back -> 2KB contiguous write bursts per warp, fewer DRAM
// read<->write turnarounds. Exact grid, no tail.

#define T_STEPS 32

__global__ void __launch_bounds__(256) if_scan_kernel(
    const float4* __restrict__ x, float4* __restrict__ y, int bn4)
{
    const unsigned i = blockIdx.x * blockDim.x + threadIdx.x;

    const float4* xp = x + i;
    float4*       yp = y + i;

    float4 v = make_float4(0.f, 0.f, 0.f, 0.f);

    #pragma unroll
    for (int t = 0; t < T_STEPS; t += 2) {
        float4 m0 = xp[(unsigned)(t + 0) * (unsigned)bn4];
        float4 m1 = xp[(unsigned)(t + 1) * (unsigned)bn4];

        float4 s0, s1;

        m0.x += v.x; m0.y += v.y; m0.z += v.z; m0.w += v.w;
        s0.x = (m0.x >= 1.0f) ? 1.0f : 0.0f;
        s0.y = (m0.y >= 1.0f) ? 1.0f : 0.0f;
        s0.z = (m0.z >= 1.0f) ? 1.0f : 0.0f;
        s0.w = (m0.w >= 1.0f) ? 1.0f : 0.0f;
        v.x = m0.x - s0.x; v.y = m0.y - s0.y; v.z = m0.z - s0.z; v.w = m0.w - s0.w;

        m1.x += v.x; m1.y += v.y; m1.z += v.z; m1.w += v.w;
        s1.x = (m1.x >= 1.0f) ? 1.0f : 0.0f;
        s1.y = (m1.y >= 1.0f) ? 1.0f : 0.0f;
        s1.z = (m1.z >= 1.0f) ? 1.0f : 0.0f;
        s1.w = (m1.w >= 1.0f) ? 1.0f : 0.0f;
        v.x = m1.x - s1.x; v.y = m1.y - s1.y; v.z = m1.z - s1.z; v.w = m1.w - s1.w;

        // paired stores, back-to-back
        yp[(unsigned)(t + 0) * (unsigned)bn4] = s0;
        yp[(unsigned)(t + 1) * (unsigned)bn4] = s1;
    }
}

extern "C" void kernel_launch(void* const* d_in, const int* in_sizes, int n_in,
                              void* d_out, int out_size)
{
    const float4* x = (const float4*)d_in[0];
    float4* y = (float4*)d_out;

    int total = in_sizes[0];           // T*B*N
    int bn = total / T_STEPS;          // B*N columns
    int bn4 = bn / 4;                  // 524288 float4 groups

    int threads = 256;
    int blocks = bn4 / threads;        // 2048, exact, no tail
    if_scan_kernel<<<blocks, threads>>>(x, y, bn4);
}